// round 16
// baseline (speedup 1.0000x reference)
#include <cuda_runtime.h>
#include <cuda_fp16.h>
#include <math.h>
#include <stdint.h>

// ---------------------------------------------------------------------------
// ForegroundAttentionModule, B=4, C=512, T=2048, fp32 in/out.
// fp16 mma.sync GEMMs (f32 accum), single product (validated rel_err ~4e-5).
// Algebra: key_ einsum collapses; q.k row-constant cancels in softmax -> kT
//   eliminated, wksum folded into q epilogue. z = colsum(v) - y, and
//   colsum(v) = Wv@featsum + T*bv  =>  vsumWl via u = Wl^T Wv (NO data pass).
// Softmax fused at zero extra barriers: qk epi -> rowmax atomicMax;
//   av transforms its own cp.async bytes pre-barrier. y.Wl fused in av epi.
// R16 head/tail cleanup: convertw folded into wksum (grid (2,32));
//   rowmaxu/yl zeroing moved into wksum; vsumwl merged into score.
// GEMM (proven R15 config): CTA 128x128, K chunk 64, 3-stage cp.async
// pipeline (prefetch 2, wait<1>), ldmatrix x4 A / x2 B, 8 warps (4M x 2N).
// ---------------------------------------------------------------------------

namespace {

constexpr int B = 4;
constexpr int C = 512;
constexpr int T = 2048;
constexpr float LN_EPS = 1e-5f;
constexpr float INV_SQRT_C = 0.04419417382415922f;

constexpr int ROW_BYTES   = 144;                 // 64 fp16 + 16B pad
constexpr int TILE_BYTES  = 128 * ROW_BYTES;     // 18432
constexpr int STAGE_BYTES = 2 * TILE_BYTES;      // A + B = 36864
constexpr int NSTAGES     = 3;
constexpr int SMEM_BYTES  = NSTAGES * STAGE_BYTES;   // 110592
constexpr int SMEM_AV     = SMEM_BYTES + 512;        // + rowsum[128]

// ---------------- device scratch -------------------------------------------
__device__ __half g_featT[(size_t)B * T * C];   // [B,T,C]
__device__ __half g_q[(size_t)B * T * C];       // [B,T,C] (pre-scaled by wksum)
__device__ __half g_vT[(size_t)B * C * T];      // [B,C,T]
__device__ __half g_y[(size_t)B * T * C];       // [B,T,C]
__device__ __half g_fh[(size_t)B * T * T];      // [B,T,T] raw logits
__device__ __half g_Wq[C * C], g_Wv[C * C], g_Ws[C * C];
__device__ uint32_t g_rowmaxu[B * T];           // encoded row max of logits
__device__ float  g_yl[B * T];                  // y . Wl (fused in av)
__device__ float  g_wksum[C];                   // sum_o Wk[o,c]
__device__ float  g_u[C];                       // sum_o Wl[o]*Wv[o,c]
__device__ float  g_featsum[B * C];             // sum_t feat[b,c,t]
__device__ double g_lnsum[B], g_lnsq[B];

// monotone float<->uint encoding for atomicMax over signed floats
__device__ __forceinline__ uint32_t enc_f(float v) {
    uint32_t u = __float_as_uint(v);
    return (u & 0x80000000u) ? ~u : (u | 0x80000000u);
}
__device__ __forceinline__ float dec_f(uint32_t k) {
    return (k & 0x80000000u) ? __uint_as_float(k & 0x7FFFFFFFu)
                             : __uint_as_float(~k);
}

// ---------------- helpers ---------------------------------------------------
__device__ __forceinline__ void mma16816(float* c, uint32_t a0, uint32_t a1,
                                         uint32_t a2, uint32_t a3,
                                         uint32_t b0, uint32_t b1) {
    asm volatile(
        "mma.sync.aligned.m16n8k16.row.col.f32.f16.f16.f32 "
        "{%0,%1,%2,%3}, {%4,%5,%6,%7}, {%8,%9}, {%0,%1,%2,%3};"
        : "+f"(c[0]), "+f"(c[1]), "+f"(c[2]), "+f"(c[3])
        : "r"(a0), "r"(a1), "r"(a2), "r"(a3), "r"(b0), "r"(b1));
}

__device__ __forceinline__ void ldsm_x4(uint32_t& r0, uint32_t& r1,
                                        uint32_t& r2, uint32_t& r3, uint32_t addr) {
    asm volatile("ldmatrix.sync.aligned.m8n8.x4.shared.b16 {%0,%1,%2,%3}, [%4];"
                 : "=r"(r0), "=r"(r1), "=r"(r2), "=r"(r3) : "r"(addr));
}
__device__ __forceinline__ void ldsm_x2(uint32_t& r0, uint32_t& r1, uint32_t addr) {
    asm volatile("ldmatrix.sync.aligned.m8n8.x2.shared.b16 {%0,%1}, [%2];"
                 : "=r"(r0), "=r"(r1) : "r"(addr));
}

__device__ __forceinline__ void cp_async16(uint32_t saddr, const void* g) {
    asm volatile("cp.async.cg.shared.global [%0], [%1], 16;" ::"r"(saddr), "l"(g));
}
__device__ __forceinline__ void cp_commit() {
    asm volatile("cp.async.commit_group;" ::: "memory");
}
template <int N>
__device__ __forceinline__ void cp_wait() {
    asm volatile("cp.async.wait_group %0;" ::"n"(N) : "memory");
}

// One 128x64 fp16 tile -> smem stage (4 x 16B per thread).
// Thread tid writes rows (tid>>3)+32p (p=0..3), 16B at q = tid&7.
__device__ __forceinline__ void load_tile(const __half* __restrict__ src,
                                          int ld, int k0, uint32_t sbase, int tid) {
#pragma unroll
    for (int p = 0; p < 4; ++p) {
        int i = tid + p * 256;
        int row = i >> 3, q = i & 7;
        cp_async16(sbase + (uint32_t)(row * ROW_BYTES + q * 16),
                   src + (size_t)row * ld + k0 + q * 8);
    }
}

// ---------------------------------------------------------------------------
// GEMM mainloop: K-chunk 64, 3-stage pipeline (prefetch 2, wait<1>).
// ---------------------------------------------------------------------------
__device__ __forceinline__ void gemm_mainloop(
    const __half* __restrict__ A, int ldA,
    const __half* __restrict__ Bm, int ldB,
    int kTotal, char* smem, float acc[2][8][4]) {
    const int tid = threadIdx.x;
    const int wid = tid >> 5, lane = tid & 31;
    const int wm = wid & 3, wn = wid >> 2;
    const uint32_t sbase = (uint32_t)__cvta_generic_to_shared(smem);
    const int nch = kTotal / 64;

    const uint32_t aOff = (uint32_t)((wm * 32 + (lane & 15)) * ROW_BYTES + (lane >> 4) * 16);
    const uint32_t bOff = (uint32_t)(TILE_BYTES +
                          (wn * 64 + (lane & 7)) * ROW_BYTES + ((lane >> 3) & 1) * 16);

#pragma unroll
    for (int s = 0; s < 2; ++s) {
        load_tile(A,  ldA, s * 64, sbase + s * STAGE_BYTES, tid);
        load_tile(Bm, ldB, s * 64, sbase + s * STAGE_BYTES + TILE_BYTES, tid);
        cp_commit();
    }

    int s_use = 0, s_fill = 2;
    for (int kc = 0; kc < nch; ++kc) {
        cp_wait<1>();
        __syncthreads();
        if (kc + 2 < nch) {
            uint32_t st = sbase + (uint32_t)(s_fill * STAGE_BYTES);
            load_tile(A,  ldA, (kc + 2) * 64, st, tid);
            load_tile(Bm, ldB, (kc + 2) * 64, st + TILE_BYTES, tid);
        }
        cp_commit();

        const uint32_t sg = sbase + (uint32_t)(s_use * STAGE_BYTES);
#pragma unroll
        for (int ks = 0; ks < 4; ++ks) {
            uint32_t a[2][4];
            ldsm_x4(a[0][0], a[0][1], a[0][2], a[0][3], sg + aOff + ks * 32);
            ldsm_x4(a[1][0], a[1][1], a[1][2], a[1][3], sg + aOff + 16 * ROW_BYTES + ks * 32);
#pragma unroll
            for (int an = 0; an < 8; ++an) {
                uint32_t b0, b1;
                ldsm_x2(b0, b1, sg + bOff + an * 8 * ROW_BYTES + ks * 32);
                mma16816(acc[0][an], a[0][0], a[0][1], a[0][2], a[0][3], b0, b1);
                mma16816(acc[1][an], a[1][0], a[1][1], a[1][2], a[1][3], b0, b1);
            }
        }
        if (++s_use == NSTAGES) s_use = 0;
        if (++s_fill == NSTAGES) s_fill = 0;
    }
}

#define EPI_COORDS()                                   \
    const int wid = threadIdx.x >> 5;                  \
    const int lane = threadIdx.x & 31;                 \
    const int wm = wid & 3, wn = wid >> 2;             \
    const int lr = lane >> 2, lc = lane & 3;

// ---------------------------------------------------------------------------
// GEMM kernels
// ---------------------------------------------------------------------------

// Merged projections. z = b + B*which: which=0 -> q', which=1 -> vT.
__global__ __launch_bounds__(256, 2) void gemm_qv_kernel(const float* __restrict__ bq,
                                                         const float* __restrict__ bv) {
    extern __shared__ char smem[];
    const int b = blockIdx.z & (B - 1), which = blockIdx.z >> 2;
    const int t0 = blockIdx.x * 128, o0 = blockIdx.y * 128;
    float acc[2][8][4] = {};
    if (which == 0) {
        gemm_mainloop(g_featT + ((size_t)b * T + t0) * C, C,
                      g_Wq + (size_t)o0 * C, C, C, smem, acc);
    } else {
        gemm_mainloop(g_Wv + (size_t)o0 * C, C,
                      g_featT + ((size_t)b * T + t0) * C, C, C, smem, acc);
    }
    EPI_COORDS();
    if (which == 0) {
#pragma unroll
        for (int am = 0; am < 2; ++am) {
            const int t = t0 + wm * 32 + am * 16 + lr;
#pragma unroll
            for (int an = 0; an < 8; ++an) {
                const int o = o0 + wn * 64 + an * 8 + lc * 2;
                const float b0 = bq[o], b1 = bq[o + 1];
                const float w0 = g_wksum[o], w1 = g_wksum[o + 1];
#pragma unroll
                for (int rr = 0; rr < 2; ++rr) {
                    const size_t idx = ((size_t)b * T + t + rr * 8) * C + o;
                    *reinterpret_cast<__half2*>(&g_q[idx]) = __floats2half2_rn(
                        (acc[am][an][rr * 2] + b0) * w0,
                        (acc[am][an][rr * 2 + 1] + b1) * w1);
                }
            }
        }
    } else {
#pragma unroll
        for (int am = 0; am < 2; ++am) {
            const int o = o0 + wm * 32 + am * 16 + lr;
#pragma unroll
            for (int an = 0; an < 8; ++an) {
                const int t = t0 + wn * 64 + an * 8 + lc * 2;
#pragma unroll
                for (int rr = 0; rr < 2; ++rr) {
                    const int oo = o + rr * 8;
                    const float bo = bv[oo];
                    const size_t idx = ((size_t)b * C + oo) * T + t;
                    *reinterpret_cast<__half2*>(&g_vT[idx]) = __floats2half2_rn(
                        acc[am][an][rr * 2] + bo, acc[am][an][rr * 2 + 1] + bo);
                }
            }
        }
    }
}

// logits f[b,t,s] = (q' @ featT^T) * inv_sqrt_c -> fp16, + row max atomicMax
__global__ __launch_bounds__(256, 2) void gemm_qk_kernel() {
    extern __shared__ char smem[];
    const int b = blockIdx.z, s0 = blockIdx.x * 128, t0 = blockIdx.y * 128;
    float acc[2][8][4] = {};
    gemm_mainloop(g_q + ((size_t)b * T + t0) * C, C,
                  g_featT + ((size_t)b * T + s0) * C, C, C, smem, acc);
    EPI_COORDS();
#pragma unroll
    for (int am = 0; am < 2; ++am) {
#pragma unroll
        for (int rr = 0; rr < 2; ++rr) {
            const int t = t0 + wm * 32 + am * 16 + lr + rr * 8;
            float rmax = -1e30f;
#pragma unroll
            for (int an = 0; an < 8; ++an) {
                const int s = s0 + wn * 64 + an * 8 + lc * 2;
                float v0 = acc[am][an][rr * 2] * INV_SQRT_C;
                float v1 = acc[am][an][rr * 2 + 1] * INV_SQRT_C;
                *reinterpret_cast<__half2*>(&g_fh[((size_t)b * T + t) * T + s]) =
                    __floats2half2_rn(v0, v1);
                rmax = fmaxf(rmax, fmaxf(v0, v1));
            }
            rmax = fmaxf(rmax, __shfl_xor_sync(0xFFFFFFFFu, rmax, 1));
            rmax = fmaxf(rmax, __shfl_xor_sync(0xFFFFFFFFu, rmax, 2));
            if (lc == 0)
                atomicMax(&g_rowmaxu[(size_t)b * T + t], enc_f(rmax));
        }
    }
}

// y[b,t,c] = softmax(f) @ vT^T -> fp16, + fused y.Wl partials.
// Fused exp on own cp.async bytes: rows (tid>>3)+32p, 16B at (tid&7)*16.
__global__ __launch_bounds__(256, 2) void gemm_av_kernel(const float* __restrict__ Wl) {
    extern __shared__ char smem[];
    const int b = blockIdx.z, c0 = blockIdx.x * 128, t0 = blockIdx.y * 128;
    const int tid = threadIdx.x;
    const int wid = tid >> 5, lane = tid & 31;
    const int wm = wid & 3, wn = wid >> 2;
    const uint32_t sbase = (uint32_t)__cvta_generic_to_shared(smem);
    const __half* A  = g_fh + ((size_t)b * T + t0) * T;   // logits rows
    const __half* Bm = g_vT + ((size_t)b * C + c0) * T;
    const int nch = T / 64;
    float acc[2][8][4] = {};
    float* rowsum = reinterpret_cast<float*>(smem + SMEM_BYTES);

    // transform ownership (matches load_tile): rows r0+32p, 16B at qq*16
    const int r0 = tid >> 3, qq = tid & 7;
    const __half2 l2e = __float2half2_rn(1.44269504f);
    __half2 mx[4];
#pragma unroll
    for (int p = 0; p < 4; ++p)
        mx[p] = __float2half2_rn(
            dec_f(g_rowmaxu[(size_t)b * T + t0 + r0 + 32 * p]) * 1.44269504f);
    float rs[4] = {};

    const uint32_t aOff = (uint32_t)((wm * 32 + (lane & 15)) * ROW_BYTES + (lane >> 4) * 16);
    const uint32_t bOff = (uint32_t)(TILE_BYTES +
                          (wn * 64 + (lane & 7)) * ROW_BYTES + ((lane >> 3) & 1) * 16);

#pragma unroll
    for (int s = 0; s < 2; ++s) {
        load_tile(A,  T, s * 64, sbase + s * STAGE_BYTES, tid);
        load_tile(Bm, T, s * 64, sbase + s * STAGE_BYTES + TILE_BYTES, tid);
        cp_commit();
    }

    int s_use = 0, s_fill = 2;
    for (int kc = 0; kc < nch; ++kc) {
        cp_wait<1>();
        // Transform own bytes of the A tile (stage s_use): logits -> exp.
        {
            char* stg = smem + s_use * STAGE_BYTES;
#pragma unroll
            for (int p = 0; p < 4; ++p) {
                __half2* ptr = reinterpret_cast<__half2*>(
                    stg + (r0 + 32 * p) * ROW_BYTES + qq * 16);
#pragma unroll
                for (int j = 0; j < 4; ++j) {
                    __half2 e = h2exp2(__hfma2(ptr[j], l2e, __hneg2(mx[p])));
                    ptr[j] = e;
                    float2 f = __half22float2(e);
                    rs[p] += f.x + f.y;
                }
            }
        }
        __syncthreads();
        if (kc + 2 < nch) {
            uint32_t st = sbase + (uint32_t)(s_fill * STAGE_BYTES);
            load_tile(A,  T, (kc + 2) * 64, st, tid);
            load_tile(Bm, T, (kc + 2) * 64, st + TILE_BYTES, tid);
        }
        cp_commit();

        const uint32_t sg = sbase + (uint32_t)(s_use * STAGE_BYTES);
#pragma unroll
        for (int ks = 0; ks < 4; ++ks) {
            uint32_t a[2][4];
            ldsm_x4(a[0][0], a[0][1], a[0][2], a[0][3], sg + aOff + ks * 32);
            ldsm_x4(a[1][0], a[1][1], a[1][2], a[1][3], sg + aOff + 16 * ROW_BYTES + ks * 32);
#pragma unroll
            for (int an = 0; an < 8; ++an) {
                uint32_t b0, b1;
                ldsm_x2(b0, b1, sg + bOff + an * 8 * ROW_BYTES + ks * 32);
                mma16816(acc[0][an], a[0][0], a[0][1], a[0][2], a[0][3], b0, b1);
                mma16816(acc[1][an], a[1][0], a[1][1], a[1][2], a[1][3], b0, b1);
            }
        }
        if (++s_use == NSTAGES) s_use = 0;
        if (++s_fill == NSTAGES) s_fill = 0;
    }

    // publish row sums (reduce over the 8 qq-threads of each row)
#pragma unroll
    for (int p = 0; p < 4; ++p) {
        rs[p] += __shfl_xor_sync(0xFFFFFFFFu, rs[p], 1);
        rs[p] += __shfl_xor_sync(0xFFFFFFFFu, rs[p], 2);
        rs[p] += __shfl_xor_sync(0xFFFFFFFFu, rs[p], 4);
    }
    __syncthreads();
    if (qq == 0) {
#pragma unroll
        for (int p = 0; p < 4; ++p) rowsum[r0 + 32 * p] = rs[p];
    }
    __syncthreads();

    const int lr = lane >> 2, lc = lane & 3;
#pragma unroll
    for (int am = 0; am < 2; ++am) {
#pragma unroll
        for (int rr = 0; rr < 2; ++rr) {
            const int lrow = wm * 32 + am * 16 + lr + rr * 8;
            const int t = t0 + lrow;
            const float inv = 1.0f / rowsum[lrow];
            float ylp = 0.0f;
#pragma unroll
            for (int an = 0; an < 8; ++an) {
                const int c = c0 + wn * 64 + an * 8 + lc * 2;
                const size_t idx = ((size_t)b * T + t) * C + c;
                const float v0 = acc[am][an][rr * 2] * inv;
                const float v1 = acc[am][an][rr * 2 + 1] * inv;
                *reinterpret_cast<__half2*>(&g_y[idx]) = __floats2half2_rn(v0, v1);
                ylp += v0 * Wl[c] + v1 * Wl[c + 1];
            }
            ylp += __shfl_xor_sync(0xFFFFFFFFu, ylp, 1);
            ylp += __shfl_xor_sync(0xFFFFFFFFu, ylp, 2);
            if (lc == 0) atomicAdd(&g_yl[(size_t)b * T + t], ylp);
        }
    }
}

// out[b,o,t] = feat + Ws @ y^T + bs; fused LN pass-1 partials.
__global__ __launch_bounds__(256, 2) void gemm_smooth_kernel(const float* __restrict__ bs,
                                                             const float* __restrict__ feat,
                                                             float* __restrict__ out) {
    extern __shared__ char smem[];
    const int b = blockIdx.z, t0 = blockIdx.x * 128, o0 = blockIdx.y * 128;
    float acc[2][8][4] = {};
    gemm_mainloop(g_Ws + (size_t)o0 * C, C,
                  g_y + ((size_t)b * T + t0) * C, C, C, smem, acc);
    EPI_COORDS();
    float psum = 0.0f, psq = 0.0f;
#pragma unroll
    for (int am = 0; am < 2; ++am) {
        const int o = o0 + wm * 32 + am * 16 + lr;
#pragma unroll
        for (int an = 0; an < 8; ++an) {
            const int t = t0 + wn * 64 + an * 8 + lc * 2;
#pragma unroll
            for (int rr = 0; rr < 2; ++rr) {
                const int oo = o + rr * 8;
                const float bo = bs[oo];
                const size_t idx = ((size_t)b * C + oo) * T + t;
                float2 fv = *reinterpret_cast<const float2*>(&feat[idx]);
                float2 v;
                v.x = fv.x + acc[am][an][rr * 2] + bo;
                v.y = fv.y + acc[am][an][rr * 2 + 1] + bo;
                *reinterpret_cast<float2*>(&out[idx]) = v;
                psum += v.x + v.y;
                psq  += v.x * v.x + v.y * v.y;
            }
        }
    }
    __syncthreads();
    float* red = reinterpret_cast<float*>(smem);
#pragma unroll
    for (int off = 16; off > 0; off >>= 1) {
        psum += __shfl_xor_sync(0xFFFFFFFFu, psum, off);
        psq  += __shfl_xor_sync(0xFFFFFFFFu, psq,  off);
    }
    if (lane == 0) { red[wid] = psum; red[8 + wid] = psq; }
    __syncthreads();
    if (threadIdx.x == 0) {
        float s = 0.0f, q = 0.0f;
#pragma unroll
        for (int w = 0; w < 8; ++w) { s += red[w]; q += red[8 + w]; }
        atomicAdd(&g_lnsum[b], (double)s);
        atomicAdd(&g_lnsq[b],  (double)q);
    }
}

// ---------------------------------------------------------------------------
// Elementwise / reduction kernels
// ---------------------------------------------------------------------------
// Zero accumulators that wksum itself atomically updates (plus LN sums).
__global__ void init_kernel() {
    const int i = blockIdx.x * 256 + threadIdx.x;   // 3072 threads
    if (i < C) { g_wksum[i] = 0.0f; g_u[i] = 0.0f; }
    if (i < B * C) g_featsum[i] = 0.0f;
    if (i < B) { g_lnsum[i] = 0.0; g_lnsq[i] = 0.0; }
}

// Merged head: per (o,c) visited once -> convert Wq/Wv/Ws to fp16; accumulate
// wksum/u partials (atomicAdd). Also zero rowmaxu and yl (consumed only by
// later kernels; stream order guarantees visibility).
// Grid (2, 32): c = bx*256+tid, o-chunk = by*16.
__global__ void wksum_kernel(const float* __restrict__ Wk,
                             const float* __restrict__ Wq,
                             const float* __restrict__ Wv,
                             const float* __restrict__ Ws,
                             const float* __restrict__ Wl) {
    const int tid = threadIdx.x;
    const int c = blockIdx.x * 256 + tid;           // 0..511
    const int o0 = blockIdx.y * 16;                 // 32 chunks of 16 rows

    // zero rowmaxu / yl: 64 blocks x 256 threads = 16384 = 2 * B*T
    const int gid = (blockIdx.y * 2 + blockIdx.x) * 256 + tid;
    if (gid < B * T) g_rowmaxu[gid] = 0;            // encoded -inf
    else             g_yl[gid - B * T] = 0.0f;

    float s = 0.0f, su = 0.0f;
#pragma unroll
    for (int o = o0; o < o0 + 16; ++o) {
        const size_t i = (size_t)o * C + c;
        const float wv = Wv[i];
        s  += Wk[i];
        su += Wl[o] * wv;
        g_Wv[i] = __float2half_rn(wv);
        g_Wq[i] = __float2half_rn(Wq[i]);
        g_Ws[i] = __float2half_rn(Ws[i]);
    }
    atomicAdd(&g_wksum[c], s);
    atomicAdd(&g_u[c], su);
}

// feat [B,C,T] -> featT fp16 [B,T,C]; featsum[b,c] += partial column sums.
__global__ void transpose_kernel(const float* __restrict__ feat) {
    __shared__ float tile[32][33];
    const int b = blockIdx.z;
    const int t0 = blockIdx.x * 32, c0 = blockIdx.y * 32;
    const int tx = threadIdx.x, ty = threadIdx.y;
#pragma unroll
    for (int i = 0; i < 4; ++i)
        tile[ty + 8 * i][tx] = feat[((size_t)b * C + c0 + ty + 8 * i) * T + t0 + tx];
    __syncthreads();
    const int c = c0 + tx;
    float fs = 0.0f;
#pragma unroll
    for (int i = 0; i < 4; ++i) {
        const int t = t0 + ty + 8 * i;
        const float v = tile[tx][ty + 8 * i];
        g_featT[((size_t)b * T + t) * C + c] = __float2half_rn(v);
        fs += v;
    }
    __syncthreads();
    tile[ty][tx] = fs;
    __syncthreads();
    if (ty == 0) {
        float s = 0.0f;
#pragma unroll
        for (int j = 0; j < 8; ++j) s += tile[j][tx];
        atomicAdd(&g_featsum[b * C + c], s);
    }
}

// score (merged vsumwl): each block covers 256 rows of one batch b.
// Block computes vsumWl[b] = sum_c (u[c]*featsum[b,c] + T*Wl[c]*bv[c])
// cooperatively, then emits elementwise scores from fused y.Wl sums.
__global__ __launch_bounds__(256) void score_kernel(const float* __restrict__ Wl,
                                                    const float* __restrict__ bv,
                                                    const float* __restrict__ bl,
                                                    float* __restrict__ score) {
    __shared__ float red[256];
    const int tid = threadIdx.x;
    const int row0 = blockIdx.x * 256;
    const int b = row0 >> 11;  // / T (T = 2048); 256 | 2048 so b uniform in block
    float s = 0.0f;
#pragma unroll
    for (int k = 0; k < 2; ++k) {
        const int c = tid + k * 256;
        s += g_u[c] * g_featsum[b * C + c] + (float)T * Wl[c] * bv[c];
    }
    red[tid] = s;
    __syncthreads();
    for (int off = 128; off > 0; off >>= 1) {
        if (tid < off) red[tid] += red[tid + off];
        __syncthreads();
    }
    const float vsumWl = red[0];

    const int row = row0 + tid;
    const float yl = g_yl[row];
    const float zl = vsumWl - yl;
    const float b0 = bl[0];
    const float fs = 1.0f / (1.0f + expf(-(yl + b0)));
    const float bsc = 1.0f - 1.0f / (1.0f + expf(-(zl + b0)));
    score[row] = 0.5f * (fs + bsc);
}

__global__ void ln2_kernel(float* __restrict__ out) {
    const int b = blockIdx.y;
    const int i = blockIdx.x * 256 + threadIdx.x;
    const double n = (double)(C * T);
    double mu = g_lnsum[b] / n;
    double var = g_lnsq[b] / n - mu * mu;
    float muf = (float)mu;
    float inv = rsqrtf((float)var + LN_EPS);
    size_t oi = (size_t)b * C * T + i;
    out[oi] = (out[oi] - muf) * inv;
}

}  // namespace

// ---------------------------------------------------------------------------
extern "C" void kernel_launch(void* const* d_in, const int* in_sizes, int n_in,
                              void* d_out, int out_size) {
    const float* feat = (const float*)d_in[0];
    const float* Wq   = (const float*)d_in[1];
    const float* bq   = (const float*)d_in[2];
    const float* Wk   = (const float*)d_in[3];
    const float* bk   = (const float*)d_in[4];  // unused: cancels in softmax
    const float* Wv   = (const float*)d_in[5];
    const float* bv   = (const float*)d_in[6];
    const float* Ws   = (const float*)d_in[7];
    const float* bs   = (const float*)d_in[8];
    const float* Wl   = (const float*)d_in[9];
    const float* bl   = (const float*)d_in[10];
    float* out = (float*)d_out;
    float* score = out + (size_t)B * C * T;
    (void)bk;

    cudaFuncSetAttribute(gemm_qv_kernel,     cudaFuncAttributeMaxDynamicSharedMemorySize, SMEM_BYTES);
    cudaFuncSetAttribute(gemm_qk_kernel,     cudaFuncAttributeMaxDynamicSharedMemorySize, SMEM_BYTES);
    cudaFuncSetAttribute(gemm_av_kernel,     cudaFuncAttributeMaxDynamicSharedMemorySize, SMEM_AV);
    cudaFuncSetAttribute(gemm_smooth_kernel, cudaFuncAttributeMaxDynamicSharedMemorySize, SMEM_BYTES);

    init_kernel<<<12, 256>>>();
    wksum_kernel<<<dim3(2, 32), 256>>>(Wk, Wq, Wv, Ws, Wl);
    transpose_kernel<<<dim3(T / 32, C / 32, B), dim3(32, 8)>>>(feat);

    gemm_qv_kernel<<<dim3(T / 128, C / 128, 2 * B), 256, SMEM_BYTES>>>(bq, bv);
    gemm_qk_kernel<<<dim3(T / 128, T / 128, B), 256, SMEM_BYTES>>>();
    gemm_av_kernel<<<dim3(C / 128, T / 128, B), 256, SMEM_AV>>>(Wl);

    score_kernel<<<(B * T) / 256, 256>>>(Wl, bv, bl, score);

    gemm_smooth_kernel<<<dim3(T / 128, C / 128, B), 256, SMEM_BYTES>>>(bs, feat, out);

    ln2_kernel<<<dim3((C * T) / 256, B), 256>>>(out);
}

// round 17
// speedup vs baseline: 1.4636x; 1.4636x over previous
#include <cuda_runtime.h>
#include <cuda_fp16.h>
#include <math.h>
#include <stdint.h>

// ---------------------------------------------------------------------------
// ForegroundAttentionModule, B=4, C=512, T=2048, fp32 in/out.
// fp16 mma.sync GEMMs (f32 accum), single product (validated rel_err ~4e-5).
// Algebra: key_ einsum collapses; q.k row-constant cancels in softmax -> kT
//   eliminated, wksum folded into q epilogue. z = colsum(v) - y, and
//   colsum(v) = Wv@featsum + T*bv  =>  vsumWl via u = Wl^T Wv (NO data pass).
// Softmax fused at zero extra barriers: qk epi -> rowmax atomicMax;
//   av transforms its own cp.async bytes pre-barrier. y.Wl fused in av epi.
// R17 = R15 base (best 256.7us) + vsumwl merged into score (tail-only).
//   R16's convertw->wksum fold REVERTED: it serialized weight conversion on
//   the critical path (normalized ~+10us).
// GEMM (proven R15 config): CTA 128x128, K chunk 64, 3-stage cp.async
// pipeline (prefetch 2, wait<1>), ldmatrix x4 A / x2 B, 8 warps (4M x 2N).
// ---------------------------------------------------------------------------

namespace {

constexpr int B = 4;
constexpr int C = 512;
constexpr int T = 2048;
constexpr float LN_EPS = 1e-5f;
constexpr float INV_SQRT_C = 0.04419417382415922f;

constexpr int ROW_BYTES   = 144;                 // 64 fp16 + 16B pad
constexpr int TILE_BYTES  = 128 * ROW_BYTES;     // 18432
constexpr int STAGE_BYTES = 2 * TILE_BYTES;      // A + B = 36864
constexpr int NSTAGES     = 3;
constexpr int SMEM_BYTES  = NSTAGES * STAGE_BYTES;   // 110592
constexpr int SMEM_AV     = SMEM_BYTES + 512;        // + rowsum[128]

// ---------------- device scratch -------------------------------------------
__device__ __half g_featT[(size_t)B * T * C];   // [B,T,C]
__device__ __half g_q[(size_t)B * T * C];       // [B,T,C] (pre-scaled by wksum)
__device__ __half g_vT[(size_t)B * C * T];      // [B,C,T]
__device__ __half g_y[(size_t)B * T * C];       // [B,T,C]
__device__ __half g_fh[(size_t)B * T * T];      // [B,T,T] raw logits
__device__ __half g_Wq[C * C], g_Wv[C * C], g_Ws[C * C];
__device__ uint32_t g_rowmaxu[B * T];           // encoded row max of logits
__device__ float  g_yl[B * T];                  // y . Wl (fused in av)
__device__ float  g_wksum[C];                   // sum_o Wk[o,c]
__device__ float  g_u[C];                       // sum_o Wl[o]*Wv[o,c]
__device__ float  g_featsum[B * C];             // sum_t feat[b,c,t]
__device__ double g_lnsum[B], g_lnsq[B];

// monotone float<->uint encoding for atomicMax over signed floats
__device__ __forceinline__ uint32_t enc_f(float v) {
    uint32_t u = __float_as_uint(v);
    return (u & 0x80000000u) ? ~u : (u | 0x80000000u);
}
__device__ __forceinline__ float dec_f(uint32_t k) {
    return (k & 0x80000000u) ? __uint_as_float(k & 0x7FFFFFFFu)
                             : __uint_as_float(~k);
}

// ---------------- helpers ---------------------------------------------------
__device__ __forceinline__ void mma16816(float* c, uint32_t a0, uint32_t a1,
                                         uint32_t a2, uint32_t a3,
                                         uint32_t b0, uint32_t b1) {
    asm volatile(
        "mma.sync.aligned.m16n8k16.row.col.f32.f16.f16.f32 "
        "{%0,%1,%2,%3}, {%4,%5,%6,%7}, {%8,%9}, {%0,%1,%2,%3};"
        : "+f"(c[0]), "+f"(c[1]), "+f"(c[2]), "+f"(c[3])
        : "r"(a0), "r"(a1), "r"(a2), "r"(a3), "r"(b0), "r"(b1));
}

__device__ __forceinline__ void ldsm_x4(uint32_t& r0, uint32_t& r1,
                                        uint32_t& r2, uint32_t& r3, uint32_t addr) {
    asm volatile("ldmatrix.sync.aligned.m8n8.x4.shared.b16 {%0,%1,%2,%3}, [%4];"
                 : "=r"(r0), "=r"(r1), "=r"(r2), "=r"(r3) : "r"(addr));
}
__device__ __forceinline__ void ldsm_x2(uint32_t& r0, uint32_t& r1, uint32_t addr) {
    asm volatile("ldmatrix.sync.aligned.m8n8.x2.shared.b16 {%0,%1}, [%2];"
                 : "=r"(r0), "=r"(r1) : "r"(addr));
}

__device__ __forceinline__ void cp_async16(uint32_t saddr, const void* g) {
    asm volatile("cp.async.cg.shared.global [%0], [%1], 16;" ::"r"(saddr), "l"(g));
}
__device__ __forceinline__ void cp_commit() {
    asm volatile("cp.async.commit_group;" ::: "memory");
}
template <int N>
__device__ __forceinline__ void cp_wait() {
    asm volatile("cp.async.wait_group %0;" ::"n"(N) : "memory");
}

// One 128x64 fp16 tile -> smem stage (4 x 16B per thread).
// Thread tid writes rows (tid>>3)+32p (p=0..3), 16B at q = tid&7.
__device__ __forceinline__ void load_tile(const __half* __restrict__ src,
                                          int ld, int k0, uint32_t sbase, int tid) {
#pragma unroll
    for (int p = 0; p < 4; ++p) {
        int i = tid + p * 256;
        int row = i >> 3, q = i & 7;
        cp_async16(sbase + (uint32_t)(row * ROW_BYTES + q * 16),
                   src + (size_t)row * ld + k0 + q * 8);
    }
}

// ---------------------------------------------------------------------------
// GEMM mainloop: K-chunk 64, 3-stage pipeline (prefetch 2, wait<1>).
// ---------------------------------------------------------------------------
__device__ __forceinline__ void gemm_mainloop(
    const __half* __restrict__ A, int ldA,
    const __half* __restrict__ Bm, int ldB,
    int kTotal, char* smem, float acc[2][8][4]) {
    const int tid = threadIdx.x;
    const int wid = tid >> 5, lane = tid & 31;
    const int wm = wid & 3, wn = wid >> 2;
    const uint32_t sbase = (uint32_t)__cvta_generic_to_shared(smem);
    const int nch = kTotal / 64;

    const uint32_t aOff = (uint32_t)((wm * 32 + (lane & 15)) * ROW_BYTES + (lane >> 4) * 16);
    const uint32_t bOff = (uint32_t)(TILE_BYTES +
                          (wn * 64 + (lane & 7)) * ROW_BYTES + ((lane >> 3) & 1) * 16);

#pragma unroll
    for (int s = 0; s < 2; ++s) {
        load_tile(A,  ldA, s * 64, sbase + s * STAGE_BYTES, tid);
        load_tile(Bm, ldB, s * 64, sbase + s * STAGE_BYTES + TILE_BYTES, tid);
        cp_commit();
    }

    int s_use = 0, s_fill = 2;
    for (int kc = 0; kc < nch; ++kc) {
        cp_wait<1>();
        __syncthreads();
        if (kc + 2 < nch) {
            uint32_t st = sbase + (uint32_t)(s_fill * STAGE_BYTES);
            load_tile(A,  ldA, (kc + 2) * 64, st, tid);
            load_tile(Bm, ldB, (kc + 2) * 64, st + TILE_BYTES, tid);
        }
        cp_commit();

        const uint32_t sg = sbase + (uint32_t)(s_use * STAGE_BYTES);
#pragma unroll
        for (int ks = 0; ks < 4; ++ks) {
            uint32_t a[2][4];
            ldsm_x4(a[0][0], a[0][1], a[0][2], a[0][3], sg + aOff + ks * 32);
            ldsm_x4(a[1][0], a[1][1], a[1][2], a[1][3], sg + aOff + 16 * ROW_BYTES + ks * 32);
#pragma unroll
            for (int an = 0; an < 8; ++an) {
                uint32_t b0, b1;
                ldsm_x2(b0, b1, sg + bOff + an * 8 * ROW_BYTES + ks * 32);
                mma16816(acc[0][an], a[0][0], a[0][1], a[0][2], a[0][3], b0, b1);
                mma16816(acc[1][an], a[1][0], a[1][1], a[1][2], a[1][3], b0, b1);
            }
        }
        if (++s_use == NSTAGES) s_use = 0;
        if (++s_fill == NSTAGES) s_fill = 0;
    }
}

#define EPI_COORDS()                                   \
    const int wid = threadIdx.x >> 5;                  \
    const int lane = threadIdx.x & 31;                 \
    const int wm = wid & 3, wn = wid >> 2;             \
    const int lr = lane >> 2, lc = lane & 3;

// ---------------------------------------------------------------------------
// GEMM kernels
// ---------------------------------------------------------------------------

// Merged projections. z = b + B*which: which=0 -> q', which=1 -> vT.
__global__ __launch_bounds__(256, 2) void gemm_qv_kernel(const float* __restrict__ bq,
                                                         const float* __restrict__ bv) {
    extern __shared__ char smem[];
    const int b = blockIdx.z & (B - 1), which = blockIdx.z >> 2;
    const int t0 = blockIdx.x * 128, o0 = blockIdx.y * 128;
    float acc[2][8][4] = {};
    if (which == 0) {
        gemm_mainloop(g_featT + ((size_t)b * T + t0) * C, C,
                      g_Wq + (size_t)o0 * C, C, C, smem, acc);
    } else {
        gemm_mainloop(g_Wv + (size_t)o0 * C, C,
                      g_featT + ((size_t)b * T + t0) * C, C, C, smem, acc);
    }
    EPI_COORDS();
    if (which == 0) {
#pragma unroll
        for (int am = 0; am < 2; ++am) {
            const int t = t0 + wm * 32 + am * 16 + lr;
#pragma unroll
            for (int an = 0; an < 8; ++an) {
                const int o = o0 + wn * 64 + an * 8 + lc * 2;
                const float b0 = bq[o], b1 = bq[o + 1];
                const float w0 = g_wksum[o], w1 = g_wksum[o + 1];
#pragma unroll
                for (int rr = 0; rr < 2; ++rr) {
                    const size_t idx = ((size_t)b * T + t + rr * 8) * C + o;
                    *reinterpret_cast<__half2*>(&g_q[idx]) = __floats2half2_rn(
                        (acc[am][an][rr * 2] + b0) * w0,
                        (acc[am][an][rr * 2 + 1] + b1) * w1);
                }
            }
        }
    } else {
#pragma unroll
        for (int am = 0; am < 2; ++am) {
            const int o = o0 + wm * 32 + am * 16 + lr;
#pragma unroll
            for (int an = 0; an < 8; ++an) {
                const int t = t0 + wn * 64 + an * 8 + lc * 2;
#pragma unroll
                for (int rr = 0; rr < 2; ++rr) {
                    const int oo = o + rr * 8;
                    const float bo = bv[oo];
                    const size_t idx = ((size_t)b * C + oo) * T + t;
                    *reinterpret_cast<__half2*>(&g_vT[idx]) = __floats2half2_rn(
                        acc[am][an][rr * 2] + bo, acc[am][an][rr * 2 + 1] + bo);
                }
            }
        }
    }
}

// logits f[b,t,s] = (q' @ featT^T) * inv_sqrt_c -> fp16, + row max atomicMax
__global__ __launch_bounds__(256, 2) void gemm_qk_kernel() {
    extern __shared__ char smem[];
    const int b = blockIdx.z, s0 = blockIdx.x * 128, t0 = blockIdx.y * 128;
    float acc[2][8][4] = {};
    gemm_mainloop(g_q + ((size_t)b * T + t0) * C, C,
                  g_featT + ((size_t)b * T + s0) * C, C, C, smem, acc);
    EPI_COORDS();
#pragma unroll
    for (int am = 0; am < 2; ++am) {
#pragma unroll
        for (int rr = 0; rr < 2; ++rr) {
            const int t = t0 + wm * 32 + am * 16 + lr + rr * 8;
            float rmax = -1e30f;
#pragma unroll
            for (int an = 0; an < 8; ++an) {
                const int s = s0 + wn * 64 + an * 8 + lc * 2;
                float v0 = acc[am][an][rr * 2] * INV_SQRT_C;
                float v1 = acc[am][an][rr * 2 + 1] * INV_SQRT_C;
                *reinterpret_cast<__half2*>(&g_fh[((size_t)b * T + t) * T + s]) =
                    __floats2half2_rn(v0, v1);
                rmax = fmaxf(rmax, fmaxf(v0, v1));
            }
            rmax = fmaxf(rmax, __shfl_xor_sync(0xFFFFFFFFu, rmax, 1));
            rmax = fmaxf(rmax, __shfl_xor_sync(0xFFFFFFFFu, rmax, 2));
            if (lc == 0)
                atomicMax(&g_rowmaxu[(size_t)b * T + t], enc_f(rmax));
        }
    }
}

// y[b,t,c] = softmax(f) @ vT^T -> fp16, + fused y.Wl partials.
// Fused exp on own cp.async bytes: rows (tid>>3)+32p, 16B at (tid&7)*16.
__global__ __launch_bounds__(256, 2) void gemm_av_kernel(const float* __restrict__ Wl) {
    extern __shared__ char smem[];
    const int b = blockIdx.z, c0 = blockIdx.x * 128, t0 = blockIdx.y * 128;
    const int tid = threadIdx.x;
    const int wid = tid >> 5, lane = tid & 31;
    const int wm = wid & 3, wn = wid >> 2;
    const uint32_t sbase = (uint32_t)__cvta_generic_to_shared(smem);
    const __half* A  = g_fh + ((size_t)b * T + t0) * T;   // logits rows
    const __half* Bm = g_vT + ((size_t)b * C + c0) * T;
    const int nch = T / 64;
    float acc[2][8][4] = {};
    float* rowsum = reinterpret_cast<float*>(smem + SMEM_BYTES);

    // transform ownership (matches load_tile): rows r0+32p, 16B at qq*16
    const int r0 = tid >> 3, qq = tid & 7;
    const __half2 l2e = __float2half2_rn(1.44269504f);
    __half2 mx[4];
#pragma unroll
    for (int p = 0; p < 4; ++p)
        mx[p] = __float2half2_rn(
            dec_f(g_rowmaxu[(size_t)b * T + t0 + r0 + 32 * p]) * 1.44269504f);
    float rs[4] = {};

    const uint32_t aOff = (uint32_t)((wm * 32 + (lane & 15)) * ROW_BYTES + (lane >> 4) * 16);
    const uint32_t bOff = (uint32_t)(TILE_BYTES +
                          (wn * 64 + (lane & 7)) * ROW_BYTES + ((lane >> 3) & 1) * 16);

#pragma unroll
    for (int s = 0; s < 2; ++s) {
        load_tile(A,  T, s * 64, sbase + s * STAGE_BYTES, tid);
        load_tile(Bm, T, s * 64, sbase + s * STAGE_BYTES + TILE_BYTES, tid);
        cp_commit();
    }

    int s_use = 0, s_fill = 2;
    for (int kc = 0; kc < nch; ++kc) {
        cp_wait<1>();
        // Transform own bytes of the A tile (stage s_use): logits -> exp.
        {
            char* stg = smem + s_use * STAGE_BYTES;
#pragma unroll
            for (int p = 0; p < 4; ++p) {
                __half2* ptr = reinterpret_cast<__half2*>(
                    stg + (r0 + 32 * p) * ROW_BYTES + qq * 16);
#pragma unroll
                for (int j = 0; j < 4; ++j) {
                    __half2 e = h2exp2(__hfma2(ptr[j], l2e, __hneg2(mx[p])));
                    ptr[j] = e;
                    float2 f = __half22float2(e);
                    rs[p] += f.x + f.y;
                }
            }
        }
        __syncthreads();
        if (kc + 2 < nch) {
            uint32_t st = sbase + (uint32_t)(s_fill * STAGE_BYTES);
            load_tile(A,  T, (kc + 2) * 64, st, tid);
            load_tile(Bm, T, (kc + 2) * 64, st + TILE_BYTES, tid);
        }
        cp_commit();

        const uint32_t sg = sbase + (uint32_t)(s_use * STAGE_BYTES);
#pragma unroll
        for (int ks = 0; ks < 4; ++ks) {
            uint32_t a[2][4];
            ldsm_x4(a[0][0], a[0][1], a[0][2], a[0][3], sg + aOff + ks * 32);
            ldsm_x4(a[1][0], a[1][1], a[1][2], a[1][3], sg + aOff + 16 * ROW_BYTES + ks * 32);
#pragma unroll
            for (int an = 0; an < 8; ++an) {
                uint32_t b0, b1;
                ldsm_x2(b0, b1, sg + bOff + an * 8 * ROW_BYTES + ks * 32);
                mma16816(acc[0][an], a[0][0], a[0][1], a[0][2], a[0][3], b0, b1);
                mma16816(acc[1][an], a[1][0], a[1][1], a[1][2], a[1][3], b0, b1);
            }
        }
        if (++s_use == NSTAGES) s_use = 0;
        if (++s_fill == NSTAGES) s_fill = 0;
    }

    // publish row sums (reduce over the 8 qq-threads of each row)
#pragma unroll
    for (int p = 0; p < 4; ++p) {
        rs[p] += __shfl_xor_sync(0xFFFFFFFFu, rs[p], 1);
        rs[p] += __shfl_xor_sync(0xFFFFFFFFu, rs[p], 2);
        rs[p] += __shfl_xor_sync(0xFFFFFFFFu, rs[p], 4);
    }
    __syncthreads();
    if (qq == 0) {
#pragma unroll
        for (int p = 0; p < 4; ++p) rowsum[r0 + 32 * p] = rs[p];
    }
    __syncthreads();

    const int lr = lane >> 2, lc = lane & 3;
#pragma unroll
    for (int am = 0; am < 2; ++am) {
#pragma unroll
        for (int rr = 0; rr < 2; ++rr) {
            const int lrow = wm * 32 + am * 16 + lr + rr * 8;
            const int t = t0 + lrow;
            const float inv = 1.0f / rowsum[lrow];
            float ylp = 0.0f;
#pragma unroll
            for (int an = 0; an < 8; ++an) {
                const int c = c0 + wn * 64 + an * 8 + lc * 2;
                const size_t idx = ((size_t)b * T + t) * C + c;
                const float v0 = acc[am][an][rr * 2] * inv;
                const float v1 = acc[am][an][rr * 2 + 1] * inv;
                *reinterpret_cast<__half2*>(&g_y[idx]) = __floats2half2_rn(v0, v1);
                ylp += v0 * Wl[c] + v1 * Wl[c + 1];
            }
            ylp += __shfl_xor_sync(0xFFFFFFFFu, ylp, 1);
            ylp += __shfl_xor_sync(0xFFFFFFFFu, ylp, 2);
            if (lc == 0) atomicAdd(&g_yl[(size_t)b * T + t], ylp);
        }
    }
}

// out[b,o,t] = feat + Ws @ y^T + bs; fused LN pass-1 partials.
__global__ __launch_bounds__(256, 2) void gemm_smooth_kernel(const float* __restrict__ bs,
                                                             const float* __restrict__ feat,
                                                             float* __restrict__ out) {
    extern __shared__ char smem[];
    const int b = blockIdx.z, t0 = blockIdx.x * 128, o0 = blockIdx.y * 128;
    float acc[2][8][4] = {};
    gemm_mainloop(g_Ws + (size_t)o0 * C, C,
                  g_y + ((size_t)b * T + t0) * C, C, C, smem, acc);
    EPI_COORDS();
    float psum = 0.0f, psq = 0.0f;
#pragma unroll
    for (int am = 0; am < 2; ++am) {
        const int o = o0 + wm * 32 + am * 16 + lr;
#pragma unroll
        for (int an = 0; an < 8; ++an) {
            const int t = t0 + wn * 64 + an * 8 + lc * 2;
#pragma unroll
            for (int rr = 0; rr < 2; ++rr) {
                const int oo = o + rr * 8;
                const float bo = bs[oo];
                const size_t idx = ((size_t)b * C + oo) * T + t;
                float2 fv = *reinterpret_cast<const float2*>(&feat[idx]);
                float2 v;
                v.x = fv.x + acc[am][an][rr * 2] + bo;
                v.y = fv.y + acc[am][an][rr * 2 + 1] + bo;
                *reinterpret_cast<float2*>(&out[idx]) = v;
                psum += v.x + v.y;
                psq  += v.x * v.x + v.y * v.y;
            }
        }
    }
    __syncthreads();
    float* red = reinterpret_cast<float*>(smem);
#pragma unroll
    for (int off = 16; off > 0; off >>= 1) {
        psum += __shfl_xor_sync(0xFFFFFFFFu, psum, off);
        psq  += __shfl_xor_sync(0xFFFFFFFFu, psq,  off);
    }
    if (lane == 0) { red[wid] = psum; red[8 + wid] = psq; }
    __syncthreads();
    if (threadIdx.x == 0) {
        float s = 0.0f, q = 0.0f;
#pragma unroll
        for (int w = 0; w < 8; ++w) { s += red[w]; q += red[8 + w]; }
        atomicAdd(&g_lnsum[b], (double)s);
        atomicAdd(&g_lnsq[b],  (double)q);
    }
}

// ---------------------------------------------------------------------------
// Elementwise / reduction kernels
// ---------------------------------------------------------------------------
// Zero all per-call accumulators (device globals persist across graph replays).
__global__ void init_kernel() {
    const int i = blockIdx.x * 256 + threadIdx.x;   // 8192 threads
    g_rowmaxu[i] = 0;       // encoded -inf
    g_yl[i] = 0.0f;
    if (i < C) { g_wksum[i] = 0.0f; g_u[i] = 0.0f; }
    if (i < B * C) g_featsum[i] = 0.0f;
    if (i < B) { g_lnsum[i] = 0.0; g_lnsq[i] = 0.0; }
}

// wksum[c] += partial sum_o Wk[o,c]; u[c] += partial sum_o Wl[o]*Wv[o,c].
__global__ void wksum_kernel(const float* __restrict__ Wk,
                             const float* __restrict__ Wv,
                             const float* __restrict__ Wl) {
    const int c = blockIdx.x * 256 + threadIdx.x;   // 0..511
    const int o0 = blockIdx.y * 64;                 // 8 chunks of 64 rows
    float s = 0.0f, su = 0.0f;
#pragma unroll 8
    for (int o = o0; o < o0 + 64; ++o) {
        s  += Wk[(size_t)o * C + c];
        su += Wl[o] * Wv[(size_t)o * C + c];
    }
    atomicAdd(&g_wksum[c], s);
    atomicAdd(&g_u[c], su);
}

// feat [B,C,T] -> featT fp16 [B,T,C]; featsum[b,c] += partial column sums.
__global__ void transpose_kernel(const float* __restrict__ feat) {
    __shared__ float tile[32][33];
    const int b = blockIdx.z;
    const int t0 = blockIdx.x * 32, c0 = blockIdx.y * 32;
    const int tx = threadIdx.x, ty = threadIdx.y;
#pragma unroll
    for (int i = 0; i < 4; ++i)
        tile[ty + 8 * i][tx] = feat[((size_t)b * C + c0 + ty + 8 * i) * T + t0 + tx];
    __syncthreads();
    const int c = c0 + tx;
    float fs = 0.0f;
#pragma unroll
    for (int i = 0; i < 4; ++i) {
        const int t = t0 + ty + 8 * i;
        const float v = tile[tx][ty + 8 * i];
        g_featT[((size_t)b * T + t) * C + c] = __float2half_rn(v);
        fs += v;
    }
    __syncthreads();
    tile[ty][tx] = fs;
    __syncthreads();
    if (ty == 0) {
        float s = 0.0f;
#pragma unroll
        for (int j = 0; j < 8; ++j) s += tile[j][tx];
        atomicAdd(&g_featsum[b * C + c], s);
    }
}

__global__ void convertw_kernel(const float* __restrict__ Wq,
                                const float* __restrict__ Wv,
                                const float* __restrict__ Ws) {
    int i = blockIdx.x * 256 + threadIdx.x;
    if (i >= C * C) return;
    g_Wq[i] = __float2half_rn(Wq[i]);
    g_Wv[i] = __float2half_rn(Wv[i]);
    g_Ws[i] = __float2half_rn(Ws[i]);
}

// score (merged vsumwl): each block covers 256 rows of one batch b.
// Block computes vsumWl[b] = sum_c (u[c]*featsum[b,c] + T*Wl[c]*bv[c])
// cooperatively, then emits elementwise scores from fused y.Wl sums.
__global__ __launch_bounds__(256) void score_kernel(const float* __restrict__ Wl,
                                                    const float* __restrict__ bv,
                                                    const float* __restrict__ bl,
                                                    float* __restrict__ score) {
    __shared__ float red[256];
    const int tid = threadIdx.x;
    const int row0 = blockIdx.x * 256;
    const int b = row0 >> 11;  // / T; 256 | 2048 so b uniform in block
    float s = 0.0f;
#pragma unroll
    for (int k = 0; k < 2; ++k) {
        const int c = tid + k * 256;
        s += g_u[c] * g_featsum[b * C + c] + (float)T * Wl[c] * bv[c];
    }
    red[tid] = s;
    __syncthreads();
    for (int off = 128; off > 0; off >>= 1) {
        if (tid < off) red[tid] += red[tid + off];
        __syncthreads();
    }
    const float vsumWl = red[0];

    const int row = row0 + tid;
    const float yl = g_yl[row];
    const float zl = vsumWl - yl;
    const float b0 = bl[0];
    const float fs = 1.0f / (1.0f + expf(-(yl + b0)));
    const float bsc = 1.0f - 1.0f / (1.0f + expf(-(zl + b0)));
    score[row] = 0.5f * (fs + bsc);
}

__global__ void ln2_kernel(float* __restrict__ out) {
    const int b = blockIdx.y;
    const int i = blockIdx.x * 256 + threadIdx.x;
    const double n = (double)(C * T);
    double mu = g_lnsum[b] / n;
    double var = g_lnsq[b] / n - mu * mu;
    float muf = (float)mu;
    float inv = rsqrtf((float)var + LN_EPS);
    size_t oi = (size_t)b * C * T + i;
    out[oi] = (out[oi] - muf) * inv;
}

}  // namespace

// ---------------------------------------------------------------------------
extern "C" void kernel_launch(void* const* d_in, const int* in_sizes, int n_in,
                              void* d_out, int out_size) {
    const float* feat = (const float*)d_in[0];
    const float* Wq   = (const float*)d_in[1];
    const float* bq   = (const float*)d_in[2];
    const float* Wk   = (const float*)d_in[3];
    const float* bk   = (const float*)d_in[4];  // unused: cancels in softmax
    const float* Wv   = (const float*)d_in[5];
    const float* bv   = (const float*)d_in[6];
    const float* Ws   = (const float*)d_in[7];
    const float* bs   = (const float*)d_in[8];
    const float* Wl   = (const float*)d_in[9];
    const float* bl   = (const float*)d_in[10];
    float* out = (float*)d_out;
    float* score = out + (size_t)B * C * T;
    (void)bk;

    cudaFuncSetAttribute(gemm_qv_kernel,     cudaFuncAttributeMaxDynamicSharedMemorySize, SMEM_BYTES);
    cudaFuncSetAttribute(gemm_qk_kernel,     cudaFuncAttributeMaxDynamicSharedMemorySize, SMEM_BYTES);
    cudaFuncSetAttribute(gemm_av_kernel,     cudaFuncAttributeMaxDynamicSharedMemorySize, SMEM_AV);
    cudaFuncSetAttribute(gemm_smooth_kernel, cudaFuncAttributeMaxDynamicSharedMemorySize, SMEM_BYTES);

    init_kernel<<<(B * T) / 256, 256>>>();
    wksum_kernel<<<dim3(2, 8), 256>>>(Wk, Wv, Wl);
    transpose_kernel<<<dim3(T / 32, C / 32, B), dim3(32, 8)>>>(feat);
    convertw_kernel<<<(C * C + 255) / 256, 256>>>(Wq, Wv, Ws);

    gemm_qv_kernel<<<dim3(T / 128, C / 128, 2 * B), 256, SMEM_BYTES>>>(bq, bv);
    gemm_qk_kernel<<<dim3(T / 128, T / 128, B), 256, SMEM_BYTES>>>();
    gemm_av_kernel<<<dim3(C / 128, T / 128, B), 256, SMEM_AV>>>(Wl);

    score_kernel<<<(B * T) / 256, 256>>>(Wl, bv, bl, score);

    gemm_smooth_kernel<<<dim3(T / 128, C / 128, B), 256, SMEM_BYTES>>>(bs, feat, out);

    ln2_kernel<<<dim3((C * T) / 256, B), 256>>>(out);
}